// round 15
// baseline (speedup 1.0000x reference)
#include <cuda_runtime.h>
#include <cuda_bf16.h>
#include <cuda_fp16.h>
#include <cstdint>

// ---------------------------------------------------------------------------
// Problem constants
// ---------------------------------------------------------------------------
#define BB 2
#define LL 2048
#define DIM 2048
#define NH 16
#define NKV 8
#define HD 128
#define WIN 128
#define NREP (NH / NKV)
#define MROWS (BB * LL)        // 4096
#define BK 32
#define NQKV (NH * HD + 2 * NKV * HD)   // 4096 fused QKV output cols

// ---------------------------------------------------------------------------
// Scratch (__device__ globals; no allocations allowed)
// ---------------------------------------------------------------------------
__device__ __half g_q16[(size_t)MROWS * NH * HD];
__device__ __half g_k16[(size_t)MROWS * NKV * HD];
__device__ __half g_v16[(size_t)MROWS * NKV * HD];

__device__ __half g_x16   [(size_t)MROWS * DIM];        // x, fp16
__device__ __half g_wqkv16[(size_t)NQKV * DIM];         // [wq;wk;wv], fp16
__device__ __half g_ao16  [(size_t)MROWS * (NH * HD)];  // attn out, fp16
__device__ __half g_wo16  [(size_t)DIM * (NH * HD)];    // wo, fp16

// ---------------------------------------------------------------------------
// PTX helpers (base sm_80+ PTX only — NO "a"-suffix features)
// ---------------------------------------------------------------------------
__device__ __forceinline__ uint32_t smem_u32(const void* p) {
    uint32_t a;
    asm("{ .reg .u64 t; cvta.to.shared.u64 t, %1; cvt.u32.u64 %0, t; }" : "=r"(a) : "l"(p));
    return a;
}
__device__ __forceinline__ void cp_async16(uint32_t dst, const void* src) {
    asm volatile("cp.async.cg.shared.global [%0], [%1], 16;"
                 :: "r"(dst), "l"(__cvta_generic_to_global(src)) : "memory");
}
__device__ __forceinline__ void cp_commit() {
    asm volatile("cp.async.commit_group;" ::: "memory");
}
template <int N>
__device__ __forceinline__ void cp_wait() {
    asm volatile("cp.async.wait_group %0;" :: "n"(N) : "memory");
}
__device__ __forceinline__ void ldsm4(uint32_t* r, uint32_t addr) {
    asm volatile("ldmatrix.sync.aligned.m8n8.x4.shared.b16 {%0,%1,%2,%3}, [%4];"
                 : "=r"(r[0]), "=r"(r[1]), "=r"(r[2]), "=r"(r[3]) : "r"(addr));
}
__device__ __forceinline__ void ldsm4t(uint32_t* r, uint32_t addr) {
    asm volatile("ldmatrix.sync.aligned.m8n8.x4.trans.shared.b16 {%0,%1,%2,%3}, [%4];"
                 : "=r"(r[0]), "=r"(r[1]), "=r"(r[2]), "=r"(r[3]) : "r"(addr));
}
__device__ __forceinline__ void mma16816(float* d, const uint32_t* a, const uint32_t* b) {
    asm volatile(
        "mma.sync.aligned.m16n8k16.row.col.f32.f16.f16.f32 "
        "{%0,%1,%2,%3}, {%4,%5,%6,%7}, {%8,%9}, {%0,%1,%2,%3};"
        : "+f"(d[0]), "+f"(d[1]), "+f"(d[2]), "+f"(d[3])
        : "r"(a[0]), "r"(a[1]), "r"(a[2]), "r"(a[3]), "r"(b[0]), "r"(b[1]));
}

// ---------------------------------------------------------------------------
// HMMA GEMM (fp16 operands): C[m, n] = sum_k A[m,k] * B[n,k]
// R11 configuration (best measured): CTA tile 128x128, BK=32, 5-stage
// cp.async pipeline, 4 warps (128 threads), warp tile 64x64, plain ks loop.
// QKV=1: fused epilogue writes q/k/v in fp16 with RoPE applied (smem-staged).
// QKV=0: plain fp32 store to C.
// ---------------------------------------------------------------------------
#define SROW 40                          // elems per smem row (32 data + 8 pad)
#define TILE_BYTES (128 * SROW * 2)      // 10240
#define STAGE_BYTES (2 * TILE_BYTES)     // A + B = 20480
#define STAGES 5
#define GEMM_SMEM (STAGES * STAGE_BYTES) // 102400

template <int QKV>
__global__ __launch_bounds__(128, 2)
void gemm_mma(const __half* __restrict__ Ag,
              const __half* __restrict__ Bg,
              float* __restrict__ C, int ldc, int kdim,
              const float* __restrict__ cosp, const float* __restrict__ sinp)
{
    extern __shared__ char smem_raw[];
    const uint32_t sb = smem_u32(smem_raw);
    const int t = threadIdx.x;
    const int lane = t & 31;
    const int wid = t >> 5;            // 0..3
    const int tile_m = blockIdx.y * 128;
    const int tile_n = blockIdx.x * 128;
    const int NTt = kdim / BK;

    const int wm = (wid & 1) * 64;     // warp row offset (0 or 64)
    const int wn = (wid >> 1) * 64;    // warp col offset (0 or 64)

    const int tsel = lane >> 3, r = lane & 7;
    uint32_t aoff[4], boff[4];
#pragma unroll
    for (int i = 0; i < 4; ++i)
        aoff[i] = ((wm + 16 * i + (tsel & 1) * 8 + r) * SROW + ((tsel & 2) ? 8 : 0)) * 2;
#pragma unroll
    for (int j = 0; j < 4; ++j)
        boff[j] = TILE_BYTES +
                  ((wn + 16 * j + ((tsel & 2) ? 8 : 0) + r) * SROW + ((tsel & 1) ? 8 : 0)) * 2;

    float acc[4][8][4];
#pragma unroll
    for (int mi = 0; mi < 4; ++mi)
#pragma unroll
        for (int ni = 0; ni < 8; ++ni)
#pragma unroll
            for (int e = 0; e < 4; ++e) acc[mi][ni][e] = 0.0f;

    auto load_stage = [&](int st, int kt) {
        uint32_t base = sb + st * STAGE_BYTES;
#pragma unroll
        for (int i = 0; i < 4; ++i) {
            int idx = t + i * 128;
            int row = idx >> 2, c = idx & 3;
            cp_async16(base + row * (SROW * 2) + c * 16,
                       Ag + (size_t)(tile_m + row) * kdim + kt * BK + c * 8);
            cp_async16(base + TILE_BYTES + row * (SROW * 2) + c * 16,
                       Bg + (size_t)(tile_n + row) * kdim + kt * BK + c * 8);
        }
    };

#pragma unroll
    for (int s = 0; s < STAGES - 1; ++s) { load_stage(s, s); cp_commit(); }

    int cs_idx = 0, ld_idx = STAGES - 1;
    for (int kt = 0; kt < NTt; ++kt) {
        cp_wait<STAGES - 2>();
        __syncthreads();

        if (kt + STAGES - 1 < NTt) load_stage(ld_idx, kt + STAGES - 1);
        cp_commit();
        if (++ld_idx == STAGES) ld_idx = 0;

        uint32_t stb = sb + cs_idx * STAGE_BYTES;
        if (++cs_idx == STAGES) cs_idx = 0;
#pragma unroll
        for (int ks = 0; ks < 2; ++ks) {
            uint32_t a[4][4], b[4][4];
#pragma unroll
            for (int mi = 0; mi < 4; ++mi) ldsm4(a[mi], stb + aoff[mi] + ks * 32);
#pragma unroll
            for (int j = 0; j < 4; ++j) ldsm4(b[j], stb + boff[j] + ks * 32);
#pragma unroll
            for (int mi = 0; mi < 4; ++mi)
#pragma unroll
                for (int j = 0; j < 4; ++j) {
                    mma16816(acc[mi][2 * j],     a[mi], &b[j][0]);
                    mma16816(acc[mi][2 * j + 1], a[mi], &b[j][2]);
                }
        }
    }

    const int g = lane >> 2, c2 = (lane & 3) * 2;

    if (QKV) {
        // Stage C tile in smem, then apply RoPE (q,k) or copy (v), store fp16
        __syncthreads();
        float* cs = (float*)smem_raw;   // 128 x 132
#pragma unroll
        for (int mi = 0; mi < 4; ++mi)
#pragma unroll
            for (int ni = 0; ni < 8; ++ni) {
                int rr = wm + 16 * mi + g;
                int cc = wn + 8 * ni + c2;
                *(float2*)&cs[rr * 132 + cc]       = make_float2(acc[mi][ni][0], acc[mi][ni][1]);
                *(float2*)&cs[(rr + 8) * 132 + cc] = make_float2(acc[mi][ni][2], acc[mi][ni][3]);
            }
        __syncthreads();

        __half* dst;
        int ldd, col0;
        bool rope;
        if (tile_n < NH * HD)                 { dst = g_q16; ldd = NH * HD;  col0 = tile_n;                  rope = true;  }
        else if (tile_n < NH * HD + NKV * HD) { dst = g_k16; ldd = NKV * HD; col0 = tile_n - NH * HD;        rope = true;  }
        else                                  { dst = g_v16; ldd = NKV * HD; col0 = tile_n - NH*HD - NKV*HD; rope = false; }

        if (rope) {
            for (int it = t; it < 128 * 64; it += 128) {
                int rr = it >> 6, d = it & 63;
                int grow = tile_m + rr;
                int l = grow & (LL - 1);
                float t1 = cs[rr * 132 + d];
                float t2 = cs[rr * 132 + d + 64];
                float c1 = cosp[l * HD + d],       s1 = sinp[l * HD + d];
                float c2f = cosp[l * HD + d + 64], s2 = sinp[l * HD + d + 64];
                dst[(size_t)grow * ldd + col0 + d]      = __float2half(t1 * c1 - t2 * s1);
                dst[(size_t)grow * ldd + col0 + d + 64] = __float2half(t2 * c2f + t1 * s2);
            }
        } else {
            for (int it = t; it < 128 * 32; it += 128) {
                int rr = it >> 5, d = (it & 31) * 4;
                float4 v = *(float4*)&cs[rr * 132 + d];
                __half2 h0 = __floats2half2_rn(v.x, v.y);
                __half2 h1 = __floats2half2_rn(v.z, v.w);
                *(uint2*)&dst[(size_t)(tile_m + rr) * ldd + col0 + d] =
                    make_uint2(*(uint32_t*)&h0, *(uint32_t*)&h1);
            }
        }
    } else {
#pragma unroll
        for (int mi = 0; mi < 4; ++mi) {
#pragma unroll
            for (int ni = 0; ni < 8; ++ni) {
                int row = tile_m + wm + 16 * mi + g;
                int col = tile_n + wn + 8 * ni + c2;
                *(float2*)(C + (size_t)row * ldc + col) =
                    make_float2(acc[mi][ni][0], acc[mi][ni][1]);
                *(float2*)(C + (size_t)(row + 8) * ldc + col) =
                    make_float2(acc[mi][ni][2], acc[mi][ni][3]);
            }
        }
    }
}

// ---------------------------------------------------------------------------
// Fused fp32 -> fp16 conversion, MLP=8: each thread converts 8 consecutive
// float4 chunks (32 floats) with independent back-to-back loads so DRAM
// latency is overlapped (the R14 version was MLP=1 latency-bound: HBM 18%).
// ---------------------------------------------------------------------------
#define CN0 ((MROWS * DIM) / 4)         // x      (float4 units)
#define CN1 ((NH * HD * DIM) / 4)       // wq
#define CN2 ((NKV * HD * DIM) / 4)      // wk
#define CN3 CN2                         // wv
#define CN4 ((DIM * NH * HD) / 4)       // wo
#define CTOT (CN0 + CN1 + CN2 + CN3 + CN4)
#define CCHUNK 8
#define CTHREADS (CTOT / CCHUNK)        // 655360 (CTOT divisible by 8)

__global__ __launch_bounds__(256)
void conv_all(const float* __restrict__ x,  const float* __restrict__ wq,
              const float* __restrict__ wk, const float* __restrict__ wv,
              const float* __restrict__ wo,
              __half* dx, __half* dwq, __half* dwk, __half* dwv, __half* dwo)
{
    int i = blockIdx.x * blockDim.x + threadIdx.x;
    if (i >= CTHREADS) return;
    int base = i * CCHUNK;   // first float4 index of this thread's run of 8

    float4 v[CCHUNK];
    const float* sp[CCHUNK];
    __half* dp[CCHUNK];
    int op[CCHUNK];
#pragma unroll
    for (int j = 0; j < CCHUNK; ++j) {
        int e = base + j;
        const float* s; __half* d; int off;
        if (e < CN0)                         { s = x;  d = dx;  off = e; }
        else if (e < CN0 + CN1)              { s = wq; d = dwq; off = e - CN0; }
        else if (e < CN0 + CN1 + CN2)        { s = wk; d = dwk; off = e - CN0 - CN1; }
        else if (e < CN0 + CN1 + CN2 + CN3)  { s = wv; d = dwv; off = e - CN0 - CN1 - CN2; }
        else                                 { s = wo; d = dwo; off = e - CN0 - CN1 - CN2 - CN3; }
        sp[j] = s; dp[j] = d; op[j] = off;
    }
    // Issue all 8 loads before any conversion/store (MLP = 8)
#pragma unroll
    for (int j = 0; j < CCHUNK; ++j)
        v[j] = *(const float4*)(sp[j] + (size_t)op[j] * 4);
#pragma unroll
    for (int j = 0; j < CCHUNK; ++j) {
        __half2 h0 = __floats2half2_rn(v[j].x, v[j].y);
        __half2 h1 = __floats2half2_rn(v[j].z, v[j].w);
        *(uint2*)(dp[j] + (size_t)op[j] * 4) = make_uint2(*(uint32_t*)&h0, *(uint32_t*)&h1);
    }
}

// ---------------------------------------------------------------------------
// Tensor-core sliding-window attention, 4-buffer smem (69.6 KB -> 2 CTA/SM).
// Block = 64 queries x 1 head; 4 warps (16 query rows each).
// Keys in 3 contiguous 64-key tiles [qt-128, qt+64). One-shot softmax.
// Buffers: b0=Q (then V2), b1=K0 (then V0), b2=K1 (then V1), b3=K2.
// __launch_bounds__(128, 2): reg cap 256 >= 255 arch max => no spill possible.
// ---------------------------------------------------------------------------
#define ATS 136                 // fp16 elems per smem row (128 + 8 pad)
#define ATSZ (64 * ATS)         // elems per 64-row tile
#define ATT_SMEM (4 * ATSZ * 2) // 69632 bytes

__global__ __launch_bounds__(128, 2)
void attn_mma_kernel()
{
    extern __shared__ __half smh[];
    const uint32_t sb = smem_u32(smh);
    const int t = threadIdx.x;
    const int lane = t & 31;
    const int w = t >> 5;
    const int qt = blockIdx.x * 64;
    const int h = blockIdx.y;
    const int b = blockIdx.z;
    const int kh = h >> 1;                 // NREP = 2
    const int tsel = lane >> 3, rr = lane & 7;
    const int kb0 = qt - 128;
    const int tf = (qt >= 128) ? 0 : ((qt >= 64) ? 1 : 2);

    auto buf = [&](int bi) { return sb + bi * (ATSZ * 2); };

    // ---- loads: g0={Q,K0?}, g1={K1?}, g2={K2}
    {
        const __half* Qg = g_q16 + ((size_t)(b * LL + qt)) * (NH * HD) + h * HD;
#pragma unroll
        for (int i = 0; i < 8; ++i) {
            int ch = t + i * 128;
            int row = ch >> 4, c = ch & 15;
            cp_async16(buf(0) + (row * ATS + c * 8) * 2, Qg + row * (NH * HD) + c * 8);
        }
    }
    auto ldK = [&](int ti, int bi) {
        const __half* Kg = g_k16 + ((size_t)(b * LL + kb0 + ti * 64)) * (NKV * HD) + kh * HD;
#pragma unroll
        for (int i = 0; i < 8; ++i) {
            int ch = t + i * 128;
            int row = ch >> 4, c = ch & 15;
            cp_async16(buf(bi) + (row * ATS + c * 8) * 2, Kg + row * (NKV * HD) + c * 8);
        }
    };
    auto ldV = [&](int ti, int bi) {
        const __half* Vg = g_v16 + ((size_t)(b * LL + kb0 + ti * 64)) * (NKV * HD) + kh * HD;
#pragma unroll
        for (int i = 0; i < 8; ++i) {
            int ch = t + i * 128;
            int row = ch >> 4, c = ch & 15;
            cp_async16(buf(bi) + (row * ATS + c * 8) * 2, Vg + row * (NKV * HD) + c * 8);
        }
    };

    if (tf <= 0) ldK(0, 1);
    cp_commit();                   // g0 = {Q, K0?}
    if (tf <= 1) ldK(1, 2);
    cp_commit();                   // g1 = {K1?}
    ldK(2, 3);
    cp_commit();                   // g2 = {K2}

    // ---- wait g0; Q fragments to registers (frees b0)
    cp_wait<2>();
    __syncthreads();
    uint32_t qf[8][4];
#pragma unroll
    for (int ds = 0; ds < 8; ++ds)
        ldsm4(qf[ds], buf(0) + ((w * 16 + (tsel & 1) * 8 + rr) * ATS +
                                ds * 16 + ((tsel & 2) ? 8 : 0)) * 2);

    float S[24][4];
#pragma unroll
    for (int blk = 0; blk < 24; ++blk)
#pragma unroll
        for (int e = 0; e < 4; ++e) S[blk][e] = 0.0f;

    auto qk_tile = [&](int ti, int bi) {
        uint32_t kbase = buf(bi);
#pragma unroll
        for (int jb = 0; jb < 4; ++jb) {
#pragma unroll
            for (int ds = 0; ds < 8; ++ds) {
                uint32_t kf[4];
                ldsm4(kf, kbase + ((jb * 16 + ((tsel & 2) ? 8 : 0) + rr) * ATS +
                                   ds * 16 + ((tsel & 1) ? 8 : 0)) * 2);
                mma16816(S[ti * 8 + 2 * jb],     qf[ds], &kf[0]);
                mma16816(S[ti * 8 + 2 * jb + 1], qf[ds], &kf[2]);
            }
        }
    };

    // tile0, then recycle b0 (Q) and b1 (K0) for V2, V0
    if (tf <= 0) qk_tile(0, 1);
    __syncthreads();               // all warps done with b0 (qf loads) and b1 (K0)
    if (tf <= 0) ldV(0, 1);
    ldV(2, 0);
    cp_commit();                   // g3 = {V0?, V2}

    cp_wait<2>();                  // g1 (K1) complete (pending: g2, g3)
    __syncthreads();
    if (tf <= 1) qk_tile(1, 2);
    __syncthreads();               // b2 (K1) free
    if (tf <= 1) ldV(1, 2);
    cp_commit();                   // g4 = {V1?}

    cp_wait<2>();                  // g2 (K2) complete (pending: g3, g4)
    __syncthreads();
    qk_tile(2, 3);

    // ---- mask + softmax (register-resident; overlaps in-flight V loads)
    const float scale = 0.08838834764831845f;
    const int g = lane >> 2, doff = (lane & 3) * 2;
    const int qlo = qt + w * 16 + g;
    const int qhi = qlo + 8;

    float mxlo = -1e30f, mxhi = -1e30f;
#pragma unroll
    for (int blk = 0; blk < 24; ++blk) {
        int k0 = kb0 + blk * 8 + doff;
        int k1 = k0 + 1;
        S[blk][0] = (k0 >= 0 && k0 <= qlo && qlo - k0 <= WIN) ? S[blk][0] * scale : -1e30f;
        S[blk][1] = (k1 >= 0 && k1 <= qlo && qlo - k1 <= WIN) ? S[blk][1] * scale : -1e30f;
        S[blk][2] = (k0 >= 0 && k0 <= qhi && qhi - k0 <= WIN) ? S[blk][2] * scale : -1e30f;
        S[blk][3] = (k1 >= 0 && k1 <= qhi && qhi - k1 <= WIN) ? S[blk][3] * scale : -1e30f;
        mxlo = fmaxf(mxlo, fmaxf(S[blk][0], S[blk][1]));
        mxhi = fmaxf(mxhi, fmaxf(S[blk][2], S[blk][3]));
    }
    mxlo = fmaxf(mxlo, __shfl_xor_sync(0xffffffffu, mxlo, 1));
    mxlo = fmaxf(mxlo, __shfl_xor_sync(0xffffffffu, mxlo, 2));
    mxhi = fmaxf(mxhi, __shfl_xor_sync(0xffffffffu, mxhi, 1));
    mxhi = fmaxf(mxhi, __shfl_xor_sync(0xffffffffu, mxhi, 2));

    float smlo = 0.0f, smhi = 0.0f;
    uint32_t P[24][2];
#pragma unroll
    for (int blk = 0; blk < 24; ++blk) {
        float e0 = __expf(S[blk][0] - mxlo);
        float e1 = __expf(S[blk][1] - mxlo);
        float e2 = __expf(S[blk][2] - mxhi);
        float e3 = __expf(S[blk][3] - mxhi);
        smlo += e0 + e1;
        smhi += e2 + e3;
        __half2 plo = __floats2half2_rn(e0, e1);
        __half2 phi = __floats2half2_rn(e2, e3);
        P[blk][0] = *(uint32_t*)&plo;
        P[blk][1] = *(uint32_t*)&phi;
    }
    smlo += __shfl_xor_sync(0xffffffffu, smlo, 1);
    smlo += __shfl_xor_sync(0xffffffffu, smlo, 2);
    smhi += __shfl_xor_sync(0xffffffffu, smhi, 1);
    smhi += __shfl_xor_sync(0xffffffffu, smhi, 2);
    float invlo = 1.0f / smlo, invhi = 1.0f / smhi;

    // ---- O = P V   (V tile ti lives in buffer vbuf[ti])
    cp_wait<0>();
    __syncthreads();

    float O[16][4];
#pragma unroll
    for (int nb = 0; nb < 16; ++nb)
#pragma unroll
        for (int e = 0; e < 4; ++e) O[nb][e] = 0.0f;

    const int vbuf0 = 1, vbuf1 = 2, vbuf2 = 0;
    const int ks0 = tf * 4;
#pragma unroll
    for (int nb = 0; nb < 8; ++nb) {
        for (int ks = ks0; ks < 12; ++ks) {
            int ti = ks >> 2;
            int bi = (ti == 0) ? vbuf0 : ((ti == 1) ? vbuf1 : vbuf2);
            int krow = (ks & 3) * 16 + (tsel & 1) * 8 + rr;
            uint32_t vf[4];
            ldsm4t(vf, buf(bi) + (krow * ATS + nb * 16 + ((tsel & 2) ? 8 : 0)) * 2);
            uint32_t A[4] = {P[2 * ks][0], P[2 * ks][1], P[2 * ks + 1][0], P[2 * ks + 1][1]};
            mma16816(O[2 * nb],     A, &vf[0]);
            mma16816(O[2 * nb + 1], A, &vf[2]);
        }
    }

    // ---- normalize + store fp16
    __half* olo = g_ao16 + ((size_t)(b * LL + qlo)) * (NH * HD) + h * HD;
    __half* ohi = g_ao16 + ((size_t)(b * LL + qhi)) * (NH * HD) + h * HD;
#pragma unroll
    for (int nb = 0; nb < 16; ++nb) {
        int d = nb * 8 + doff;
        __half2 lo = __floats2half2_rn(O[nb][0] * invlo, O[nb][1] * invlo);
        __half2 hi = __floats2half2_rn(O[nb][2] * invhi, O[nb][3] * invhi);
        *(uint32_t*)&olo[d] = *(uint32_t*)&lo;
        *(uint32_t*)&ohi[d] = *(uint32_t*)&hi;
    }
}

// ---------------------------------------------------------------------------
// Launcher
// ---------------------------------------------------------------------------
extern "C" void kernel_launch(void* const* d_in, const int* in_sizes, int n_in,
                              void* d_out, int out_size)
{
    const float* x    = (const float*)d_in[0];
    const float* cosp = (const float*)d_in[1];
    const float* sinp = (const float*)d_in[2];
    const float* wq   = (const float*)d_in[3];
    const float* wk   = (const float*)d_in[4];
    const float* wv   = (const float*)d_in[5];
    const float* wo   = (const float*)d_in[6];
    float* out = (float*)d_out;

    __half *px16, *pwqkv16, *pao16, *pwo16;
    cudaGetSymbolAddress((void**)&px16, g_x16);
    cudaGetSymbolAddress((void**)&pwqkv16, g_wqkv16);
    cudaGetSymbolAddress((void**)&pao16, g_ao16);
    cudaGetSymbolAddress((void**)&pwo16, g_wo16);

    cudaFuncSetAttribute((const void*)gemm_mma<1>, cudaFuncAttributeMaxDynamicSharedMemorySize, GEMM_SMEM);
    cudaFuncSetAttribute((const void*)gemm_mma<0>, cudaFuncAttributeMaxDynamicSharedMemorySize, GEMM_SMEM);
    cudaFuncSetAttribute((const void*)attn_mma_kernel, cudaFuncAttributeMaxDynamicSharedMemorySize, ATT_SMEM);

    // 1) fused fp32 -> fp16 conversions (x, wq, wk, wv, wo), MLP=8 per thread
    conv_all<<<(CTHREADS + 255) / 256, 256>>>(
        x, wq, wk, wv, wo,
        px16,
        pwqkv16,
        pwqkv16 + (size_t)(NH * HD) * DIM,
        pwqkv16 + (size_t)(NH * HD + NKV * HD) * DIM,
        pwo16);

    // 2) Fused QKV projection (fp16) + RoPE epilogue -> fp16 q/k/v
    gemm_mma<1><<<dim3(NQKV / 128, MROWS / 128), 128, GEMM_SMEM>>>(
        px16, pwqkv16, nullptr, 0, DIM, cosp, sinp);

    // 3) Tensor-core sliding-window attention (fp16 in/out, 2 CTA/SM)
    attn_mma_kernel<<<dim3(LL / 64, NH, BB), 128, ATT_SMEM>>>();

    // 4) Output projection: fp16, K = 2048
    gemm_mma<0><<<dim3(DIM / 128, MROWS / 128), 128, GEMM_SMEM>>>(
        pao16, pwo16, out, DIM, NH * HD, nullptr, nullptr);
}

// round 16
// speedup vs baseline: 1.0553x; 1.0553x over previous
#include <cuda_runtime.h>
#include <cuda_bf16.h>
#include <cuda_fp16.h>
#include <cstdint>

// ---------------------------------------------------------------------------
// Problem constants
// ---------------------------------------------------------------------------
#define BB 2
#define LL 2048
#define DIM 2048
#define NH 16
#define NKV 8
#define HD 128
#define WIN 128
#define NREP (NH / NKV)
#define MROWS (BB * LL)        // 4096
#define BK 32
#define NQKV (NH * HD + 2 * NKV * HD)   // 4096 fused QKV output cols

// ---------------------------------------------------------------------------
// Scratch (__device__ globals; no allocations allowed)
// ---------------------------------------------------------------------------
__device__ __half g_q16[(size_t)MROWS * NH * HD];
__device__ __half g_k16[(size_t)MROWS * NKV * HD];
__device__ __half g_v16[(size_t)MROWS * NKV * HD];

__device__ __half g_x16   [(size_t)MROWS * DIM];        // x, fp16
__device__ __half g_wqkv16[(size_t)NQKV * DIM];         // [wq;wk;wv], fp16
__device__ __half g_ao16  [(size_t)MROWS * (NH * HD)];  // attn out, fp16
__device__ __half g_wo16  [(size_t)DIM * (NH * HD)];    // wo, fp16

// ---------------------------------------------------------------------------
// PTX helpers (base sm_80+ PTX only — NO "a"-suffix features)
// ---------------------------------------------------------------------------
__device__ __forceinline__ uint32_t smem_u32(const void* p) {
    uint32_t a;
    asm("{ .reg .u64 t; cvta.to.shared.u64 t, %1; cvt.u32.u64 %0, t; }" : "=r"(a) : "l"(p));
    return a;
}
__device__ __forceinline__ void cp_async16(uint32_t dst, const void* src) {
    asm volatile("cp.async.cg.shared.global [%0], [%1], 16;"
                 :: "r"(dst), "l"(__cvta_generic_to_global(src)) : "memory");
}
__device__ __forceinline__ void cp_commit() {
    asm volatile("cp.async.commit_group;" ::: "memory");
}
template <int N>
__device__ __forceinline__ void cp_wait() {
    asm volatile("cp.async.wait_group %0;" :: "n"(N) : "memory");
}
__device__ __forceinline__ void ldsm4(uint32_t* r, uint32_t addr) {
    asm volatile("ldmatrix.sync.aligned.m8n8.x4.shared.b16 {%0,%1,%2,%3}, [%4];"
                 : "=r"(r[0]), "=r"(r[1]), "=r"(r[2]), "=r"(r[3]) : "r"(addr));
}
__device__ __forceinline__ void ldsm4t(uint32_t* r, uint32_t addr) {
    asm volatile("ldmatrix.sync.aligned.m8n8.x4.trans.shared.b16 {%0,%1,%2,%3}, [%4];"
                 : "=r"(r[0]), "=r"(r[1]), "=r"(r[2]), "=r"(r[3]) : "r"(addr));
}
__device__ __forceinline__ void mma16816(float* d, const uint32_t* a, const uint32_t* b) {
    asm volatile(
        "mma.sync.aligned.m16n8k16.row.col.f32.f16.f16.f32 "
        "{%0,%1,%2,%3}, {%4,%5,%6,%7}, {%8,%9}, {%0,%1,%2,%3};"
        : "+f"(d[0]), "+f"(d[1]), "+f"(d[2]), "+f"(d[3])
        : "r"(a[0]), "r"(a[1]), "r"(a[2]), "r"(a[3]), "r"(b[0]), "r"(b[1]));
}

// ---------------------------------------------------------------------------
// HMMA GEMM (fp16 operands): C[m, n] = sum_k A[m,k] * B[n,k]
// R11 configuration (best measured): CTA tile 128x128, BK=32, 5-stage
// cp.async pipeline, 4 warps (128 threads), warp tile 64x64, plain ks loop.
// QKV=1: fused epilogue writes q/k/v in fp16 with RoPE applied (smem-staged).
// QKV=0: plain fp32 store to C.
// ---------------------------------------------------------------------------
#define SROW 40                          // elems per smem row (32 data + 8 pad)
#define TILE_BYTES (128 * SROW * 2)      // 10240
#define STAGE_BYTES (2 * TILE_BYTES)     // A + B = 20480
#define STAGES 5
#define GEMM_SMEM (STAGES * STAGE_BYTES) // 102400

template <int QKV>
__global__ __launch_bounds__(128, 2)
void gemm_mma(const __half* __restrict__ Ag,
              const __half* __restrict__ Bg,
              float* __restrict__ C, int ldc, int kdim,
              const float* __restrict__ cosp, const float* __restrict__ sinp)
{
    extern __shared__ char smem_raw[];
    const uint32_t sb = smem_u32(smem_raw);
    const int t = threadIdx.x;
    const int lane = t & 31;
    const int wid = t >> 5;            // 0..3
    const int tile_m = blockIdx.y * 128;
    const int tile_n = blockIdx.x * 128;
    const int NTt = kdim / BK;

    const int wm = (wid & 1) * 64;     // warp row offset (0 or 64)
    const int wn = (wid >> 1) * 64;    // warp col offset (0 or 64)

    const int tsel = lane >> 3, r = lane & 7;
    uint32_t aoff[4], boff[4];
#pragma unroll
    for (int i = 0; i < 4; ++i)
        aoff[i] = ((wm + 16 * i + (tsel & 1) * 8 + r) * SROW + ((tsel & 2) ? 8 : 0)) * 2;
#pragma unroll
    for (int j = 0; j < 4; ++j)
        boff[j] = TILE_BYTES +
                  ((wn + 16 * j + ((tsel & 2) ? 8 : 0) + r) * SROW + ((tsel & 1) ? 8 : 0)) * 2;

    float acc[4][8][4];
#pragma unroll
    for (int mi = 0; mi < 4; ++mi)
#pragma unroll
        for (int ni = 0; ni < 8; ++ni)
#pragma unroll
            for (int e = 0; e < 4; ++e) acc[mi][ni][e] = 0.0f;

    auto load_stage = [&](int st, int kt) {
        uint32_t base = sb + st * STAGE_BYTES;
#pragma unroll
        for (int i = 0; i < 4; ++i) {
            int idx = t + i * 128;
            int row = idx >> 2, c = idx & 3;
            cp_async16(base + row * (SROW * 2) + c * 16,
                       Ag + (size_t)(tile_m + row) * kdim + kt * BK + c * 8);
            cp_async16(base + TILE_BYTES + row * (SROW * 2) + c * 16,
                       Bg + (size_t)(tile_n + row) * kdim + kt * BK + c * 8);
        }
    };

#pragma unroll
    for (int s = 0; s < STAGES - 1; ++s) { load_stage(s, s); cp_commit(); }

    int cs_idx = 0, ld_idx = STAGES - 1;
    for (int kt = 0; kt < NTt; ++kt) {
        cp_wait<STAGES - 2>();
        __syncthreads();

        if (kt + STAGES - 1 < NTt) load_stage(ld_idx, kt + STAGES - 1);
        cp_commit();
        if (++ld_idx == STAGES) ld_idx = 0;

        uint32_t stb = sb + cs_idx * STAGE_BYTES;
        if (++cs_idx == STAGES) cs_idx = 0;
#pragma unroll
        for (int ks = 0; ks < 2; ++ks) {
            uint32_t a[4][4], b[4][4];
#pragma unroll
            for (int mi = 0; mi < 4; ++mi) ldsm4(a[mi], stb + aoff[mi] + ks * 32);
#pragma unroll
            for (int j = 0; j < 4; ++j) ldsm4(b[j], stb + boff[j] + ks * 32);
#pragma unroll
            for (int mi = 0; mi < 4; ++mi)
#pragma unroll
                for (int j = 0; j < 4; ++j) {
                    mma16816(acc[mi][2 * j],     a[mi], &b[j][0]);
                    mma16816(acc[mi][2 * j + 1], a[mi], &b[j][2]);
                }
        }
    }

    const int g = lane >> 2, c2 = (lane & 3) * 2;

    if (QKV) {
        // Stage C tile in smem, then apply RoPE (q,k) or copy (v), store fp16
        __syncthreads();
        float* cs = (float*)smem_raw;   // 128 x 132
#pragma unroll
        for (int mi = 0; mi < 4; ++mi)
#pragma unroll
            for (int ni = 0; ni < 8; ++ni) {
                int rr = wm + 16 * mi + g;
                int cc = wn + 8 * ni + c2;
                *(float2*)&cs[rr * 132 + cc]       = make_float2(acc[mi][ni][0], acc[mi][ni][1]);
                *(float2*)&cs[(rr + 8) * 132 + cc] = make_float2(acc[mi][ni][2], acc[mi][ni][3]);
            }
        __syncthreads();

        __half* dst;
        int ldd, col0;
        bool rope;
        if (tile_n < NH * HD)                 { dst = g_q16; ldd = NH * HD;  col0 = tile_n;                  rope = true;  }
        else if (tile_n < NH * HD + NKV * HD) { dst = g_k16; ldd = NKV * HD; col0 = tile_n - NH * HD;        rope = true;  }
        else                                  { dst = g_v16; ldd = NKV * HD; col0 = tile_n - NH*HD - NKV*HD; rope = false; }

        if (rope) {
            for (int it = t; it < 128 * 64; it += 128) {
                int rr = it >> 6, d = it & 63;
                int grow = tile_m + rr;
                int l = grow & (LL - 1);
                float t1 = cs[rr * 132 + d];
                float t2 = cs[rr * 132 + d + 64];
                float c1 = cosp[l * HD + d],       s1 = sinp[l * HD + d];
                float c2f = cosp[l * HD + d + 64], s2 = sinp[l * HD + d + 64];
                dst[(size_t)grow * ldd + col0 + d]      = __float2half(t1 * c1 - t2 * s1);
                dst[(size_t)grow * ldd + col0 + d + 64] = __float2half(t2 * c2f + t1 * s2);
            }
        } else {
            for (int it = t; it < 128 * 32; it += 128) {
                int rr = it >> 5, d = (it & 31) * 4;
                float4 v = *(float4*)&cs[rr * 132 + d];
                __half2 h0 = __floats2half2_rn(v.x, v.y);
                __half2 h1 = __floats2half2_rn(v.z, v.w);
                *(uint2*)&dst[(size_t)(tile_m + rr) * ldd + col0 + d] =
                    make_uint2(*(uint32_t*)&h0, *(uint32_t*)&h1);
            }
        }
    } else {
#pragma unroll
        for (int mi = 0; mi < 4; ++mi) {
#pragma unroll
            for (int ni = 0; ni < 8; ++ni) {
                int row = tile_m + wm + 16 * mi + g;
                int col = tile_n + wn + 8 * ni + c2;
                *(float2*)(C + (size_t)row * ldc + col) =
                    make_float2(acc[mi][ni][0], acc[mi][ni][1]);
                *(float2*)(C + (size_t)(row + 8) * ldc + col) =
                    make_float2(acc[mi][ni][2], acc[mi][ni][3]);
            }
        }
    }
}

// ---------------------------------------------------------------------------
// Fused fp32 -> fp16 conversion, MLP=8 with grid-stride interleave:
// thread i handles float4 indices {i, i+CTHREADS, ..., i+7*CTHREADS} so
// adjacent lanes stay adjacent within EVERY load (coalesced, nL=8) while each
// thread keeps 8 independent loads in flight (R15's consecutive-chunk variant
// broke coalescing: 32 lines per warp load).
// ---------------------------------------------------------------------------
#define CN0 ((MROWS * DIM) / 4)         // x      (float4 units)
#define CN1 ((NH * HD * DIM) / 4)       // wq
#define CN2 ((NKV * HD * DIM) / 4)      // wk
#define CN3 CN2                         // wv
#define CN4 ((DIM * NH * HD) / 4)       // wo
#define CTOT (CN0 + CN1 + CN2 + CN3 + CN4)
#define CCHUNK 8
#define CTHREADS (CTOT / CCHUNK)        // 655360 (CTOT divisible by 8)

__global__ __launch_bounds__(256)
void conv_all(const float* __restrict__ x,  const float* __restrict__ wq,
              const float* __restrict__ wk, const float* __restrict__ wv,
              const float* __restrict__ wo,
              __half* dx, __half* dwq, __half* dwk, __half* dwv, __half* dwo)
{
    int i = blockIdx.x * blockDim.x + threadIdx.x;
    if (i >= CTHREADS) return;

    float4 v[CCHUNK];
    __half* dp[CCHUNK];
    int op[CCHUNK];
#pragma unroll
    for (int j = 0; j < CCHUNK; ++j) {
        int e = i + j * CTHREADS;
        const float* s; __half* d; int off;
        if (e < CN0)                         { s = x;  d = dx;  off = e; }
        else if (e < CN0 + CN1)              { s = wq; d = dwq; off = e - CN0; }
        else if (e < CN0 + CN1 + CN2)        { s = wk; d = dwk; off = e - CN0 - CN1; }
        else if (e < CN0 + CN1 + CN2 + CN3)  { s = wv; d = dwv; off = e - CN0 - CN1 - CN2; }
        else                                 { s = wo; d = dwo; off = e - CN0 - CN1 - CN2 - CN3; }
        v[j] = *(const float4*)(s + (size_t)off * 4);   // independent loads, MLP = 8
        dp[j] = d; op[j] = off;
    }
#pragma unroll
    for (int j = 0; j < CCHUNK; ++j) {
        __half2 h0 = __floats2half2_rn(v[j].x, v[j].y);
        __half2 h1 = __floats2half2_rn(v[j].z, v[j].w);
        *(uint2*)(dp[j] + (size_t)op[j] * 4) = make_uint2(*(uint32_t*)&h0, *(uint32_t*)&h1);
    }
}

// ---------------------------------------------------------------------------
// Tensor-core sliding-window attention, 4-buffer smem (69.6 KB -> 2 CTA/SM).
// Block = 64 queries x 1 head; 4 warps (16 query rows each).
// Keys in 3 contiguous 64-key tiles [qt-128, qt+64). One-shot softmax.
// Buffers: b0=Q (then V2), b1=K0 (then V0), b2=K1 (then V1), b3=K2.
// __launch_bounds__(128, 2): reg cap 256 >= 255 arch max => no spill possible.
// ---------------------------------------------------------------------------
#define ATS 136                 // fp16 elems per smem row (128 + 8 pad)
#define ATSZ (64 * ATS)         // elems per 64-row tile
#define ATT_SMEM (4 * ATSZ * 2) // 69632 bytes

__global__ __launch_bounds__(128, 2)
void attn_mma_kernel()
{
    extern __shared__ __half smh[];
    const uint32_t sb = smem_u32(smh);
    const int t = threadIdx.x;
    const int lane = t & 31;
    const int w = t >> 5;
    const int qt = blockIdx.x * 64;
    const int h = blockIdx.y;
    const int b = blockIdx.z;
    const int kh = h >> 1;                 // NREP = 2
    const int tsel = lane >> 3, rr = lane & 7;
    const int kb0 = qt - 128;
    const int tf = (qt >= 128) ? 0 : ((qt >= 64) ? 1 : 2);

    auto buf = [&](int bi) { return sb + bi * (ATSZ * 2); };

    // ---- loads: g0={Q,K0?}, g1={K1?}, g2={K2}
    {
        const __half* Qg = g_q16 + ((size_t)(b * LL + qt)) * (NH * HD) + h * HD;
#pragma unroll
        for (int i = 0; i < 8; ++i) {
            int ch = t + i * 128;
            int row = ch >> 4, c = ch & 15;
            cp_async16(buf(0) + (row * ATS + c * 8) * 2, Qg + row * (NH * HD) + c * 8);
        }
    }
    auto ldK = [&](int ti, int bi) {
        const __half* Kg = g_k16 + ((size_t)(b * LL + kb0 + ti * 64)) * (NKV * HD) + kh * HD;
#pragma unroll
        for (int i = 0; i < 8; ++i) {
            int ch = t + i * 128;
            int row = ch >> 4, c = ch & 15;
            cp_async16(buf(bi) + (row * ATS + c * 8) * 2, Kg + row * (NKV * HD) + c * 8);
        }
    };
    auto ldV = [&](int ti, int bi) {
        const __half* Vg = g_v16 + ((size_t)(b * LL + kb0 + ti * 64)) * (NKV * HD) + kh * HD;
#pragma unroll
        for (int i = 0; i < 8; ++i) {
            int ch = t + i * 128;
            int row = ch >> 4, c = ch & 15;
            cp_async16(buf(bi) + (row * ATS + c * 8) * 2, Vg + row * (NKV * HD) + c * 8);
        }
    };

    if (tf <= 0) ldK(0, 1);
    cp_commit();                   // g0 = {Q, K0?}
    if (tf <= 1) ldK(1, 2);
    cp_commit();                   // g1 = {K1?}
    ldK(2, 3);
    cp_commit();                   // g2 = {K2}

    // ---- wait g0; Q fragments to registers (frees b0)
    cp_wait<2>();
    __syncthreads();
    uint32_t qf[8][4];
#pragma unroll
    for (int ds = 0; ds < 8; ++ds)
        ldsm4(qf[ds], buf(0) + ((w * 16 + (tsel & 1) * 8 + rr) * ATS +
                                ds * 16 + ((tsel & 2) ? 8 : 0)) * 2);

    float S[24][4];
#pragma unroll
    for (int blk = 0; blk < 24; ++blk)
#pragma unroll
        for (int e = 0; e < 4; ++e) S[blk][e] = 0.0f;

    auto qk_tile = [&](int ti, int bi) {
        uint32_t kbase = buf(bi);
#pragma unroll
        for (int jb = 0; jb < 4; ++jb) {
#pragma unroll
            for (int ds = 0; ds < 8; ++ds) {
                uint32_t kf[4];
                ldsm4(kf, kbase + ((jb * 16 + ((tsel & 2) ? 8 : 0) + rr) * ATS +
                                   ds * 16 + ((tsel & 1) ? 8 : 0)) * 2);
                mma16816(S[ti * 8 + 2 * jb],     qf[ds], &kf[0]);
                mma16816(S[ti * 8 + 2 * jb + 1], qf[ds], &kf[2]);
            }
        }
    };

    // tile0, then recycle b0 (Q) and b1 (K0) for V2, V0
    if (tf <= 0) qk_tile(0, 1);
    __syncthreads();               // all warps done with b0 (qf loads) and b1 (K0)
    if (tf <= 0) ldV(0, 1);
    ldV(2, 0);
    cp_commit();                   // g3 = {V0?, V2}

    cp_wait<2>();                  // g1 (K1) complete (pending: g2, g3)
    __syncthreads();
    if (tf <= 1) qk_tile(1, 2);
    __syncthreads();               // b2 (K1) free
    if (tf <= 1) ldV(1, 2);
    cp_commit();                   // g4 = {V1?}

    cp_wait<2>();                  // g2 (K2) complete (pending: g3, g4)
    __syncthreads();
    qk_tile(2, 3);

    // ---- mask + softmax (register-resident; overlaps in-flight V loads)
    const float scale = 0.08838834764831845f;
    const int g = lane >> 2, doff = (lane & 3) * 2;
    const int qlo = qt + w * 16 + g;
    const int qhi = qlo + 8;

    float mxlo = -1e30f, mxhi = -1e30f;
#pragma unroll
    for (int blk = 0; blk < 24; ++blk) {
        int k0 = kb0 + blk * 8 + doff;
        int k1 = k0 + 1;
        S[blk][0] = (k0 >= 0 && k0 <= qlo && qlo - k0 <= WIN) ? S[blk][0] * scale : -1e30f;
        S[blk][1] = (k1 >= 0 && k1 <= qlo && qlo - k1 <= WIN) ? S[blk][1] * scale : -1e30f;
        S[blk][2] = (k0 >= 0 && k0 <= qhi && qhi - k0 <= WIN) ? S[blk][2] * scale : -1e30f;
        S[blk][3] = (k1 >= 0 && k1 <= qhi && qhi - k1 <= WIN) ? S[blk][3] * scale : -1e30f;
        mxlo = fmaxf(mxlo, fmaxf(S[blk][0], S[blk][1]));
        mxhi = fmaxf(mxhi, fmaxf(S[blk][2], S[blk][3]));
    }
    mxlo = fmaxf(mxlo, __shfl_xor_sync(0xffffffffu, mxlo, 1));
    mxlo = fmaxf(mxlo, __shfl_xor_sync(0xffffffffu, mxlo, 2));
    mxhi = fmaxf(mxhi, __shfl_xor_sync(0xffffffffu, mxhi, 1));
    mxhi = fmaxf(mxhi, __shfl_xor_sync(0xffffffffu, mxhi, 2));

    float smlo = 0.0f, smhi = 0.0f;
    uint32_t P[24][2];
#pragma unroll
    for (int blk = 0; blk < 24; ++blk) {
        float e0 = __expf(S[blk][0] - mxlo);
        float e1 = __expf(S[blk][1] - mxlo);
        float e2 = __expf(S[blk][2] - mxhi);
        float e3 = __expf(S[blk][3] - mxhi);
        smlo += e0 + e1;
        smhi += e2 + e3;
        __half2 plo = __floats2half2_rn(e0, e1);
        __half2 phi = __floats2half2_rn(e2, e3);
        P[blk][0] = *(uint32_t*)&plo;
        P[blk][1] = *(uint32_t*)&phi;
    }
    smlo += __shfl_xor_sync(0xffffffffu, smlo, 1);
    smlo += __shfl_xor_sync(0xffffffffu, smlo, 2);
    smhi += __shfl_xor_sync(0xffffffffu, smhi, 1);
    smhi += __shfl_xor_sync(0xffffffffu, smhi, 2);
    float invlo = 1.0f / smlo, invhi = 1.0f / smhi;

    // ---- O = P V   (V tile ti lives in buffer vbuf[ti])
    cp_wait<0>();
    __syncthreads();

    float O[16][4];
#pragma unroll
    for (int nb = 0; nb < 16; ++nb)
#pragma unroll
        for (int e = 0; e < 4; ++e) O[nb][e] = 0.0f;

    const int vbuf0 = 1, vbuf1 = 2, vbuf2 = 0;
    const int ks0 = tf * 4;
#pragma unroll
    for (int nb = 0; nb < 8; ++nb) {
        for (int ks = ks0; ks < 12; ++ks) {
            int ti = ks >> 2;
            int bi = (ti == 0) ? vbuf0 : ((ti == 1) ? vbuf1 : vbuf2);
            int krow = (ks & 3) * 16 + (tsel & 1) * 8 + rr;
            uint32_t vf[4];
            ldsm4t(vf, buf(bi) + (krow * ATS + nb * 16 + ((tsel & 2) ? 8 : 0)) * 2);
            uint32_t A[4] = {P[2 * ks][0], P[2 * ks][1], P[2 * ks + 1][0], P[2 * ks + 1][1]};
            mma16816(O[2 * nb],     A, &vf[0]);
            mma16816(O[2 * nb + 1], A, &vf[2]);
        }
    }

    // ---- normalize + store fp16
    __half* olo = g_ao16 + ((size_t)(b * LL + qlo)) * (NH * HD) + h * HD;
    __half* ohi = g_ao16 + ((size_t)(b * LL + qhi)) * (NH * HD) + h * HD;
#pragma unroll
    for (int nb = 0; nb < 16; ++nb) {
        int d = nb * 8 + doff;
        __half2 lo = __floats2half2_rn(O[nb][0] * invlo, O[nb][1] * invlo);
        __half2 hi = __floats2half2_rn(O[nb][2] * invhi, O[nb][3] * invhi);
        *(uint32_t*)&olo[d] = *(uint32_t*)&lo;
        *(uint32_t*)&ohi[d] = *(uint32_t*)&hi;
    }
}

// ---------------------------------------------------------------------------
// Launcher
// ---------------------------------------------------------------------------
extern "C" void kernel_launch(void* const* d_in, const int* in_sizes, int n_in,
                              void* d_out, int out_size)
{
    const float* x    = (const float*)d_in[0];
    const float* cosp = (const float*)d_in[1];
    const float* sinp = (const float*)d_in[2];
    const float* wq   = (const float*)d_in[3];
    const float* wk   = (const float*)d_in[4];
    const float* wv   = (const float*)d_in[5];
    const float* wo   = (const float*)d_in[6];
    float* out = (float*)d_out;

    __half *px16, *pwqkv16, *pao16, *pwo16;
    cudaGetSymbolAddress((void**)&px16, g_x16);
    cudaGetSymbolAddress((void**)&pwqkv16, g_wqkv16);
    cudaGetSymbolAddress((void**)&pao16, g_ao16);
    cudaGetSymbolAddress((void**)&pwo16, g_wo16);

    cudaFuncSetAttribute((const void*)gemm_mma<1>, cudaFuncAttributeMaxDynamicSharedMemorySize, GEMM_SMEM);
    cudaFuncSetAttribute((const void*)gemm_mma<0>, cudaFuncAttributeMaxDynamicSharedMemorySize, GEMM_SMEM);
    cudaFuncSetAttribute((const void*)attn_mma_kernel, cudaFuncAttributeMaxDynamicSharedMemorySize, ATT_SMEM);

    // 1) fused fp32 -> fp16 conversions, MLP=8 grid-stride interleave
    conv_all<<<(CTHREADS + 255) / 256, 256>>>(
        x, wq, wk, wv, wo,
        px16,
        pwqkv16,
        pwqkv16 + (size_t)(NH * HD) * DIM,
        pwqkv16 + (size_t)(NH * HD + NKV * HD) * DIM,
        pwo16);

    // 2) Fused QKV projection (fp16) + RoPE epilogue -> fp16 q/k/v
    gemm_mma<1><<<dim3(NQKV / 128, MROWS / 128), 128, GEMM_SMEM>>>(
        px16, pwqkv16, nullptr, 0, DIM, cosp, sinp);

    // 3) Tensor-core sliding-window attention (fp16 in/out, 2 CTA/SM)
    attn_mma_kernel<<<dim3(LL / 64, NH, BB), 128, ATT_SMEM>>>();

    // 4) Output projection: fp16, K = 2048
    gemm_mma<0><<<dim3(DIM / 128, MROWS / 128), 128, GEMM_SMEM>>>(
        pao16, pwo16, out, DIM, NH * HD, nullptr, nullptr);
}

// round 17
// speedup vs baseline: 1.0658x; 1.0100x over previous
#include <cuda_runtime.h>
#include <cuda_bf16.h>
#include <cuda_fp16.h>
#include <cstdint>

// ---------------------------------------------------------------------------
// Problem constants
// ---------------------------------------------------------------------------
#define BB 2
#define LL 2048
#define DIM 2048
#define NH 16
#define NKV 8
#define HD 128
#define WIN 128
#define NREP (NH / NKV)
#define MROWS (BB * LL)        // 4096
#define BK 32
#define NQKV (NH * HD + 2 * NKV * HD)   // 4096 fused QKV output cols

// ---------------------------------------------------------------------------
// Scratch (__device__ globals; no allocations allowed)
// ---------------------------------------------------------------------------
__device__ __half g_q16[(size_t)MROWS * NH * HD];
__device__ __half g_k16[(size_t)MROWS * NKV * HD];
__device__ __half g_v16[(size_t)MROWS * NKV * HD];

__device__ __half g_x16   [(size_t)MROWS * DIM];        // x, fp16
__device__ __half g_wqkv16[(size_t)NQKV * DIM];         // [wq;wk;wv], fp16
__device__ __half g_ao16  [(size_t)MROWS * (NH * HD)];  // attn out, fp16
__device__ __half g_wo16  [(size_t)DIM * (NH * HD)];    // wo, fp16

// ---------------------------------------------------------------------------
// PTX helpers (base sm_80+ PTX only — NO "a"-suffix features)
// ---------------------------------------------------------------------------
__device__ __forceinline__ uint32_t smem_u32(const void* p) {
    uint32_t a;
    asm("{ .reg .u64 t; cvta.to.shared.u64 t, %1; cvt.u32.u64 %0, t; }" : "=r"(a) : "l"(p));
    return a;
}
__device__ __forceinline__ void cp_async16(uint32_t dst, const void* src) {
    asm volatile("cp.async.cg.shared.global [%0], [%1], 16;"
                 :: "r"(dst), "l"(__cvta_generic_to_global(src)) : "memory");
}
__device__ __forceinline__ void cp_commit() {
    asm volatile("cp.async.commit_group;" ::: "memory");
}
template <int N>
__device__ __forceinline__ void cp_wait() {
    asm volatile("cp.async.wait_group %0;" :: "n"(N) : "memory");
}
__device__ __forceinline__ void ldsm4(uint32_t* r, uint32_t addr) {
    asm volatile("ldmatrix.sync.aligned.m8n8.x4.shared.b16 {%0,%1,%2,%3}, [%4];"
                 : "=r"(r[0]), "=r"(r[1]), "=r"(r[2]), "=r"(r[3]) : "r"(addr));
}
__device__ __forceinline__ void ldsm4t(uint32_t* r, uint32_t addr) {
    asm volatile("ldmatrix.sync.aligned.m8n8.x4.trans.shared.b16 {%0,%1,%2,%3}, [%4];"
                 : "=r"(r[0]), "=r"(r[1]), "=r"(r[2]), "=r"(r[3]) : "r"(addr));
}
__device__ __forceinline__ void mma16816(float* d, const uint32_t* a, const uint32_t* b) {
    asm volatile(
        "mma.sync.aligned.m16n8k16.row.col.f32.f16.f16.f32 "
        "{%0,%1,%2,%3}, {%4,%5,%6,%7}, {%8,%9}, {%0,%1,%2,%3};"
        : "+f"(d[0]), "+f"(d[1]), "+f"(d[2]), "+f"(d[3])
        : "r"(a[0]), "r"(a[1]), "r"(a[2]), "r"(a[3]), "r"(b[0]), "r"(b[1]));
}

// ---------------------------------------------------------------------------
// HMMA GEMM (fp16 operands): C[m, n] = sum_k A[m,k] * B[n,k]
// R11 configuration (best measured): CTA tile 128x128, BK=32, 5-stage
// cp.async pipeline, 4 warps (128 threads), warp tile 64x64, plain ks loop.
// QKV=1: fused epilogue writes q/k/v in fp16 with RoPE applied (smem-staged,
//        float2-vectorized). QKV=0: plain fp32 store to C.
// ---------------------------------------------------------------------------
#define SROW 40                          // elems per smem row (32 data + 8 pad)
#define TILE_BYTES (128 * SROW * 2)      // 10240
#define STAGE_BYTES (2 * TILE_BYTES)     // A + B = 20480
#define STAGES 5
#define GEMM_SMEM (STAGES * STAGE_BYTES) // 102400

template <int QKV>
__global__ __launch_bounds__(128, 2)
void gemm_mma(const __half* __restrict__ Ag,
              const __half* __restrict__ Bg,
              float* __restrict__ C, int ldc, int kdim,
              const float* __restrict__ cosp, const float* __restrict__ sinp)
{
    extern __shared__ char smem_raw[];
    const uint32_t sb = smem_u32(smem_raw);
    const int t = threadIdx.x;
    const int lane = t & 31;
    const int wid = t >> 5;            // 0..3
    const int tile_m = blockIdx.y * 128;
    const int tile_n = blockIdx.x * 128;
    const int NTt = kdim / BK;

    const int wm = (wid & 1) * 64;     // warp row offset (0 or 64)
    const int wn = (wid >> 1) * 64;    // warp col offset (0 or 64)

    const int tsel = lane >> 3, r = lane & 7;
    uint32_t aoff[4], boff[4];
#pragma unroll
    for (int i = 0; i < 4; ++i)
        aoff[i] = ((wm + 16 * i + (tsel & 1) * 8 + r) * SROW + ((tsel & 2) ? 8 : 0)) * 2;
#pragma unroll
    for (int j = 0; j < 4; ++j)
        boff[j] = TILE_BYTES +
                  ((wn + 16 * j + ((tsel & 2) ? 8 : 0) + r) * SROW + ((tsel & 1) ? 8 : 0)) * 2;

    float acc[4][8][4];
#pragma unroll
    for (int mi = 0; mi < 4; ++mi)
#pragma unroll
        for (int ni = 0; ni < 8; ++ni)
#pragma unroll
            for (int e = 0; e < 4; ++e) acc[mi][ni][e] = 0.0f;

    auto load_stage = [&](int st, int kt) {
        uint32_t base = sb + st * STAGE_BYTES;
#pragma unroll
        for (int i = 0; i < 4; ++i) {
            int idx = t + i * 128;
            int row = idx >> 2, c = idx & 3;
            cp_async16(base + row * (SROW * 2) + c * 16,
                       Ag + (size_t)(tile_m + row) * kdim + kt * BK + c * 8);
            cp_async16(base + TILE_BYTES + row * (SROW * 2) + c * 16,
                       Bg + (size_t)(tile_n + row) * kdim + kt * BK + c * 8);
        }
    };

#pragma unroll
    for (int s = 0; s < STAGES - 1; ++s) { load_stage(s, s); cp_commit(); }

    int cs_idx = 0, ld_idx = STAGES - 1;
    for (int kt = 0; kt < NTt; ++kt) {
        cp_wait<STAGES - 2>();
        __syncthreads();

        if (kt + STAGES - 1 < NTt) load_stage(ld_idx, kt + STAGES - 1);
        cp_commit();
        if (++ld_idx == STAGES) ld_idx = 0;

        uint32_t stb = sb + cs_idx * STAGE_BYTES;
        if (++cs_idx == STAGES) cs_idx = 0;
#pragma unroll
        for (int ks = 0; ks < 2; ++ks) {
            uint32_t a[4][4], b[4][4];
#pragma unroll
            for (int mi = 0; mi < 4; ++mi) ldsm4(a[mi], stb + aoff[mi] + ks * 32);
#pragma unroll
            for (int j = 0; j < 4; ++j) ldsm4(b[j], stb + boff[j] + ks * 32);
#pragma unroll
            for (int mi = 0; mi < 4; ++mi)
#pragma unroll
                for (int j = 0; j < 4; ++j) {
                    mma16816(acc[mi][2 * j],     a[mi], &b[j][0]);
                    mma16816(acc[mi][2 * j + 1], a[mi], &b[j][2]);
                }
        }
    }

    const int g = lane >> 2, c2 = (lane & 3) * 2;

    if (QKV) {
        // Stage C tile in smem, then apply RoPE (q,k) or copy (v), store fp16
        __syncthreads();
        float* cs = (float*)smem_raw;   // 128 x 132
#pragma unroll
        for (int mi = 0; mi < 4; ++mi)
#pragma unroll
            for (int ni = 0; ni < 8; ++ni) {
                int rr = wm + 16 * mi + g;
                int cc = wn + 8 * ni + c2;
                *(float2*)&cs[rr * 132 + cc]       = make_float2(acc[mi][ni][0], acc[mi][ni][1]);
                *(float2*)&cs[(rr + 8) * 132 + cc] = make_float2(acc[mi][ni][2], acc[mi][ni][3]);
            }
        __syncthreads();

        __half* dst;
        int ldd, col0;
        bool rope;
        if (tile_n < NH * HD)                 { dst = g_q16; ldd = NH * HD;  col0 = tile_n;                  rope = true;  }
        else if (tile_n < NH * HD + NKV * HD) { dst = g_k16; ldd = NKV * HD; col0 = tile_n - NH * HD;        rope = true;  }
        else                                  { dst = g_v16; ldd = NKV * HD; col0 = tile_n - NH*HD - NKV*HD; rope = false; }

        if (rope) {
            // float2-vectorized: 2 consecutive d per thread iteration
            for (int it = t; it < 128 * 32; it += 128) {
                int rr = it >> 5, d = (it & 31) * 2;
                int grow = tile_m + rr;
                int l = grow & (LL - 1);
                float2 t1 = *(float2*)&cs[rr * 132 + d];
                float2 t2 = *(float2*)&cs[rr * 132 + d + 64];
                float2 c1 = *(const float2*)&cosp[l * HD + d];
                float2 s1 = *(const float2*)&sinp[l * HD + d];
                float2 c2f = *(const float2*)&cosp[l * HD + d + 64];
                float2 s2 = *(const float2*)&sinp[l * HD + d + 64];
                __half2 o1 = __floats2half2_rn(t1.x * c1.x - t2.x * s1.x,
                                               t1.y * c1.y - t2.y * s1.y);
                __half2 o2 = __floats2half2_rn(t2.x * c2f.x + t1.x * s2.x,
                                               t2.y * c2f.y + t1.y * s2.y);
                *(uint32_t*)&dst[(size_t)grow * ldd + col0 + d]      = *(uint32_t*)&o1;
                *(uint32_t*)&dst[(size_t)grow * ldd + col0 + d + 64] = *(uint32_t*)&o2;
            }
        } else {
            for (int it = t; it < 128 * 32; it += 128) {
                int rr = it >> 5, d = (it & 31) * 4;
                float4 v = *(float4*)&cs[rr * 132 + d];
                __half2 h0 = __floats2half2_rn(v.x, v.y);
                __half2 h1 = __floats2half2_rn(v.z, v.w);
                *(uint2*)&dst[(size_t)(tile_m + rr) * ldd + col0 + d] =
                    make_uint2(*(uint32_t*)&h0, *(uint32_t*)&h1);
            }
        }
    } else {
#pragma unroll
        for (int mi = 0; mi < 4; ++mi) {
#pragma unroll
            for (int ni = 0; ni < 8; ++ni) {
                int row = tile_m + wm + 16 * mi + g;
                int col = tile_n + wn + 8 * ni + c2;
                *(float2*)(C + (size_t)row * ldc + col) =
                    make_float2(acc[mi][ni][0], acc[mi][ni][1]);
                *(float2*)(C + (size_t)(row + 8) * ldc + col) =
                    make_float2(acc[mi][ni][2], acc[mi][ni][3]);
            }
        }
    }
}

// ---------------------------------------------------------------------------
// Fused fp32 -> fp16 conversion, MLP=8 grid-stride interleave (R16 version).
// ---------------------------------------------------------------------------
#define CN0 ((MROWS * DIM) / 4)         // x      (float4 units)
#define CN1 ((NH * HD * DIM) / 4)       // wq
#define CN2 ((NKV * HD * DIM) / 4)      // wk
#define CN3 CN2                         // wv
#define CN4 ((DIM * NH * HD) / 4)       // wo
#define CTOT (CN0 + CN1 + CN2 + CN3 + CN4)
#define CCHUNK 8
#define CTHREADS (CTOT / CCHUNK)

__global__ __launch_bounds__(256)
void conv_all(const float* __restrict__ x,  const float* __restrict__ wq,
              const float* __restrict__ wk, const float* __restrict__ wv,
              const float* __restrict__ wo,
              __half* dx, __half* dwq, __half* dwk, __half* dwv, __half* dwo)
{
    int i = blockIdx.x * blockDim.x + threadIdx.x;
    if (i >= CTHREADS) return;

    float4 v[CCHUNK];
    __half* dp[CCHUNK];
    int op[CCHUNK];
#pragma unroll
    for (int j = 0; j < CCHUNK; ++j) {
        int e = i + j * CTHREADS;
        const float* s; __half* d; int off;
        if (e < CN0)                         { s = x;  d = dx;  off = e; }
        else if (e < CN0 + CN1)              { s = wq; d = dwq; off = e - CN0; }
        else if (e < CN0 + CN1 + CN2)        { s = wk; d = dwk; off = e - CN0 - CN1; }
        else if (e < CN0 + CN1 + CN2 + CN3)  { s = wv; d = dwv; off = e - CN0 - CN1 - CN2; }
        else                                 { s = wo; d = dwo; off = e - CN0 - CN1 - CN2 - CN3; }
        v[j] = *(const float4*)(s + (size_t)off * 4);
        dp[j] = d; op[j] = off;
    }
#pragma unroll
    for (int j = 0; j < CCHUNK; ++j) {
        __half2 h0 = __floats2half2_rn(v[j].x, v[j].y);
        __half2 h1 = __floats2half2_rn(v[j].z, v[j].w);
        *(uint2*)(dp[j] + (size_t)op[j] * 4) = make_uint2(*(uint32_t*)&h0, *(uint32_t*)&h1);
    }
}

// ---------------------------------------------------------------------------
// Tensor-core sliding-window attention, GQA-paired:
// Block = 64 queries x 2 q-heads sharing ONE KV head (halves K/V L2 traffic).
// 256 threads = 8 warps; warps 0-3 -> head 2*kh, warps 4-7 -> head 2*kh+1.
// Buffers: b0=Q0, b1=Q1, b2..4=K0..2, b5..7=V0..2 (139 KB, 1 CTA/SM).
// Keys in 3 contiguous 64-key tiles [qt-128, qt+64). One-shot softmax.
// Per-(b,h,q) math identical to R8/R14 -> bit-identical output.
// ---------------------------------------------------------------------------
#define ATS 136                 // fp16 elems per smem row (128 + 8 pad)
#define ATSZ (64 * ATS)         // elems per 64-row tile
#define ATT_SMEM (8 * ATSZ * 2) // 139264 bytes

__global__ __launch_bounds__(256, 1)
void attn_mma_kernel()
{
    extern __shared__ __half smh[];
    const uint32_t sb = smem_u32(smh);
    const int t = threadIdx.x;
    const int lane = t & 31;
    const int w = t >> 5;                  // 0..7
    const int hs = w >> 2;                 // head select within KV group
    const int wr = w & 3;                  // warp row group within head
    const int qt = blockIdx.x * 64;
    const int kh = blockIdx.y;
    const int b = blockIdx.z;
    const int h = kh * NREP + hs;
    const int tsel = lane >> 3, rr = lane & 7;
    const int kb0 = qt - 128;
    const int tf = (qt >= 128) ? 0 : ((qt >= 64) ? 1 : 2);

    auto buf = [&](int bi) { return sb + bi * (ATSZ * 2); };

    // ---- loads (256 threads -> 4 chunks per tile per thread)
    auto ldQ = [&](int hsel, int bi) {
        const __half* Qg = g_q16 + ((size_t)(b * LL + qt)) * (NH * HD) + (kh * NREP + hsel) * HD;
#pragma unroll
        for (int i = 0; i < 4; ++i) {
            int ch = t + i * 256;
            int row = ch >> 4, c = ch & 15;
            cp_async16(buf(bi) + (row * ATS + c * 8) * 2, Qg + row * (NH * HD) + c * 8);
        }
    };
    auto ldK = [&](int ti) {
        const __half* Kg = g_k16 + ((size_t)(b * LL + kb0 + ti * 64)) * (NKV * HD) + kh * HD;
#pragma unroll
        for (int i = 0; i < 4; ++i) {
            int ch = t + i * 256;
            int row = ch >> 4, c = ch & 15;
            cp_async16(buf(2 + ti) + (row * ATS + c * 8) * 2, Kg + row * (NKV * HD) + c * 8);
        }
    };
    auto ldV = [&](int ti) {
        const __half* Vg = g_v16 + ((size_t)(b * LL + kb0 + ti * 64)) * (NKV * HD) + kh * HD;
#pragma unroll
        for (int i = 0; i < 4; ++i) {
            int ch = t + i * 256;
            int row = ch >> 4, c = ch & 15;
            cp_async16(buf(5 + ti) + (row * ATS + c * 8) * 2, Vg + row * (NKV * HD) + c * 8);
        }
    };

    ldQ(0, 0); ldQ(1, 1);
    if (tf <= 0) { ldK(0); ldV(0); }
    cp_commit();                 // g0 = {Q0, Q1, K0?, V0?}
    if (tf <= 1) { ldK(1); ldV(1); }
    cp_commit();                 // g1 = {K1?, V1?}
    ldK(2); ldV(2);
    cp_commit();                 // g2 = {K2, V2}

    // ---- Q fragments (8 d-steps) from this warp's head buffer
    cp_wait<2>();
    __syncthreads();
    uint32_t qf[8][4];
#pragma unroll
    for (int ds = 0; ds < 8; ++ds)
        ldsm4(qf[ds], buf(hs) + ((wr * 16 + (tsel & 1) * 8 + rr) * ATS +
                                 ds * 16 + ((tsel & 2) ? 8 : 0)) * 2);

    // ---- S = Q K^T over 24 n8-blocks (192 keys)
    float S[24][4];
#pragma unroll
    for (int blk = 0; blk < 24; ++blk)
#pragma unroll
        for (int e = 0; e < 4; ++e) S[blk][e] = 0.0f;

    auto qk_tile = [&](int ti) {
        uint32_t kbase = buf(2 + ti);
#pragma unroll
        for (int jb = 0; jb < 4; ++jb) {
#pragma unroll
            for (int ds = 0; ds < 8; ++ds) {
                uint32_t kf[4];
                ldsm4(kf, kbase + ((jb * 16 + ((tsel & 2) ? 8 : 0) + rr) * ATS +
                                   ds * 16 + ((tsel & 1) ? 8 : 0)) * 2);
                mma16816(S[ti * 8 + 2 * jb],     qf[ds], &kf[0]);
                mma16816(S[ti * 8 + 2 * jb + 1], qf[ds], &kf[2]);
            }
        }
    };
    if (tf <= 0) qk_tile(0);
    cp_wait<1>();
    __syncthreads();
    if (tf <= 1) qk_tile(1);
    cp_wait<0>();
    __syncthreads();
    qk_tile(2);

    // ---- mask + softmax (register-resident)
    const float scale = 0.08838834764831845f;
    const int g = lane >> 2, doff = (lane & 3) * 2;
    const int qlo = qt + wr * 16 + g;
    const int qhi = qlo + 8;

    float mxlo = -1e30f, mxhi = -1e30f;
#pragma unroll
    for (int blk = 0; blk < 24; ++blk) {
        int k0 = kb0 + blk * 8 + doff;
        int k1 = k0 + 1;
        S[blk][0] = (k0 >= 0 && k0 <= qlo && qlo - k0 <= WIN) ? S[blk][0] * scale : -1e30f;
        S[blk][1] = (k1 >= 0 && k1 <= qlo && qlo - k1 <= WIN) ? S[blk][1] * scale : -1e30f;
        S[blk][2] = (k0 >= 0 && k0 <= qhi && qhi - k0 <= WIN) ? S[blk][2] * scale : -1e30f;
        S[blk][3] = (k1 >= 0 && k1 <= qhi && qhi - k1 <= WIN) ? S[blk][3] * scale : -1e30f;
        mxlo = fmaxf(mxlo, fmaxf(S[blk][0], S[blk][1]));
        mxhi = fmaxf(mxhi, fmaxf(S[blk][2], S[blk][3]));
    }
    mxlo = fmaxf(mxlo, __shfl_xor_sync(0xffffffffu, mxlo, 1));
    mxlo = fmaxf(mxlo, __shfl_xor_sync(0xffffffffu, mxlo, 2));
    mxhi = fmaxf(mxhi, __shfl_xor_sync(0xffffffffu, mxhi, 1));
    mxhi = fmaxf(mxhi, __shfl_xor_sync(0xffffffffu, mxhi, 2));

    float smlo = 0.0f, smhi = 0.0f;
    uint32_t P[24][2];
#pragma unroll
    for (int blk = 0; blk < 24; ++blk) {
        float e0 = __expf(S[blk][0] - mxlo);
        float e1 = __expf(S[blk][1] - mxlo);
        float e2 = __expf(S[blk][2] - mxhi);
        float e3 = __expf(S[blk][3] - mxhi);
        smlo += e0 + e1;
        smhi += e2 + e3;
        __half2 plo = __floats2half2_rn(e0, e1);
        __half2 phi = __floats2half2_rn(e2, e3);
        P[blk][0] = *(uint32_t*)&plo;
        P[blk][1] = *(uint32_t*)&phi;
    }
    smlo += __shfl_xor_sync(0xffffffffu, smlo, 1);
    smlo += __shfl_xor_sync(0xffffffffu, smlo, 2);
    smhi += __shfl_xor_sync(0xffffffffu, smhi, 1);
    smhi += __shfl_xor_sync(0xffffffffu, smhi, 2);
    float invlo = 1.0f / smlo, invhi = 1.0f / smhi;

    // ---- O = P V
    float O[16][4];
#pragma unroll
    for (int nb = 0; nb < 16; ++nb)
#pragma unroll
        for (int e = 0; e < 4; ++e) O[nb][e] = 0.0f;

    const int ks0 = tf * 4;
#pragma unroll
    for (int nb = 0; nb < 8; ++nb) {
        for (int ks = ks0; ks < 12; ++ks) {
            int ti = ks >> 2;
            int krow = (ks & 3) * 16 + (tsel & 1) * 8 + rr;
            uint32_t vf[4];
            ldsm4t(vf, buf(5 + ti) + (krow * ATS + nb * 16 + ((tsel & 2) ? 8 : 0)) * 2);
            uint32_t A[4] = {P[2 * ks][0], P[2 * ks][1], P[2 * ks + 1][0], P[2 * ks + 1][1]};
            mma16816(O[2 * nb],     A, &vf[0]);
            mma16816(O[2 * nb + 1], A, &vf[2]);
        }
    }

    // ---- normalize + store fp16
    __half* olo = g_ao16 + ((size_t)(b * LL + qlo)) * (NH * HD) + h * HD;
    __half* ohi = g_ao16 + ((size_t)(b * LL + qhi)) * (NH * HD) + h * HD;
#pragma unroll
    for (int nb = 0; nb < 16; ++nb) {
        int d = nb * 8 + doff;
        __half2 lo = __floats2half2_rn(O[nb][0] * invlo, O[nb][1] * invlo);
        __half2 hi = __floats2half2_rn(O[nb][2] * invhi, O[nb][3] * invhi);
        *(uint32_t*)&olo[d] = *(uint32_t*)&lo;
        *(uint32_t*)&ohi[d] = *(uint32_t*)&hi;
    }
}

// ---------------------------------------------------------------------------
// Launcher
// ---------------------------------------------------------------------------
extern "C" void kernel_launch(void* const* d_in, const int* in_sizes, int n_in,
                              void* d_out, int out_size)
{
    const float* x    = (const float*)d_in[0];
    const float* cosp = (const float*)d_in[1];
    const float* sinp = (const float*)d_in[2];
    const float* wq   = (const float*)d_in[3];
    const float* wk   = (const float*)d_in[4];
    const float* wv   = (const float*)d_in[5];
    const float* wo   = (const float*)d_in[6];
    float* out = (float*)d_out;

    __half *px16, *pwqkv16, *pao16, *pwo16;
    cudaGetSymbolAddress((void**)&px16, g_x16);
    cudaGetSymbolAddress((void**)&pwqkv16, g_wqkv16);
    cudaGetSymbolAddress((void**)&pao16, g_ao16);
    cudaGetSymbolAddress((void**)&pwo16, g_wo16);

    cudaFuncSetAttribute((const void*)gemm_mma<1>, cudaFuncAttributeMaxDynamicSharedMemorySize, GEMM_SMEM);
    cudaFuncSetAttribute((const void*)gemm_mma<0>, cudaFuncAttributeMaxDynamicSharedMemorySize, GEMM_SMEM);
    cudaFuncSetAttribute((const void*)attn_mma_kernel, cudaFuncAttributeMaxDynamicSharedMemorySize, ATT_SMEM);

    // 1) fused fp32 -> fp16 conversions, MLP=8 grid-stride interleave
    conv_all<<<(CTHREADS + 255) / 256, 256>>>(
        x, wq, wk, wv, wo,
        px16,
        pwqkv16,
        pwqkv16 + (size_t)(NH * HD) * DIM,
        pwqkv16 + (size_t)(NH * HD + NKV * HD) * DIM,
        pwo16);

    // 2) Fused QKV projection (fp16) + RoPE epilogue -> fp16 q/k/v
    gemm_mma<1><<<dim3(NQKV / 128, MROWS / 128), 128, GEMM_SMEM>>>(
        px16, pwqkv16, nullptr, 0, DIM, cosp, sinp);

    // 3) GQA-paired tensor-core sliding-window attention
    attn_mma_kernel<<<dim3(LL / 64, NKV, BB), 256, ATT_SMEM>>>();

    // 4) Output projection: fp16, K = 2048
    gemm_mma<0><<<dim3(DIM / 128, MROWS / 128), 128, GEMM_SMEM>>>(
        pao16, pwo16, out, DIM, NH * HD, nullptr, nullptr);
}